// round 3
// baseline (speedup 1.0000x reference)
#include <cuda_runtime.h>
#include <cuda_bf16.h>
#include <cstdint>

// MaxUnpooling2D via scatter-add.
// updates: [16,128,128,64] f32   (16,777,216 elems)        d_in[0]
// mask:    [16,128,128,64] int32 (JAX x64-disabled: int64 -> int32), d_in[1]
//          values in [0, 256*256*64)
// out:     [16,256,256,64] f32   (67,108,864 elems = 256 MB)
// out[b*OUT_FLAT + mask[i]] += updates[i]

static constexpr int N_IN     = 16 * 128 * 128 * 64;   // 16,777,216
static constexpr int OUT_FLAT = 256 * 256 * 64;        // 4,194,304 per batch
// 1<<20 input elements per batch

__global__ void zero_kernel(float4* __restrict__ out, int n4) {
    int i = blockIdx.x * blockDim.x + threadIdx.x;
    int stride = gridDim.x * blockDim.x;
    for (; i < n4; i += stride) {
        out[i] = make_float4(0.f, 0.f, 0.f, 0.f);
    }
}

__global__ void scatter_kernel(const float4* __restrict__ updates4,
                               const int4* __restrict__ mask4,
                               float* __restrict__ out) {
    int t = blockIdx.x * blockDim.x + threadIdx.x;   // one thread = 4 elements
    if (t >= N_IN / 4) return;

    int base_elem = t * 4;
    // All 4 elements share one batch: 1<<20 elems/batch divisible by 4.
    int batch = base_elem >> 20;
    long long boff = (long long)batch * OUT_FLAT;

    float4 u = updates4[t];
    int4   m = mask4[t];

    float* outb = out + boff;
    // Guard: out-of-range index must not form an address (aperture -> err 717).
    if ((unsigned)m.x < (unsigned)OUT_FLAT) atomicAdd(outb + m.x, u.x);
    if ((unsigned)m.y < (unsigned)OUT_FLAT) atomicAdd(outb + m.y, u.y);
    if ((unsigned)m.z < (unsigned)OUT_FLAT) atomicAdd(outb + m.z, u.z);
    if ((unsigned)m.w < (unsigned)OUT_FLAT) atomicAdd(outb + m.w, u.w);
}

extern "C" void kernel_launch(void* const* d_in, const int* in_sizes, int n_in,
                              void* d_out, int out_size) {
    const float4* updates4 = (const float4*)d_in[0];
    const int4*   mask4    = (const int4*)d_in[1];
    float*        out      = (float*)d_out;

    // Zero the output (harness poisons it with 0xAA).
    int n4 = out_size / 4;                          // 16,777,216 float4 stores
    {
        int threads = 256;
        int blocks  = 148 * 8;                      // grid-stride, full chip
        zero_kernel<<<blocks, threads>>>((float4*)out, n4);
    }

    // Scatter-add.
    {
        int threads = 256;
        int work    = N_IN / 4;                     // 4,194,304 threads
        int blocks  = (work + threads - 1) / threads;
        scatter_kernel<<<blocks, threads>>>(updates4, mask4, out);
    }
}